// round 3
// baseline (speedup 1.0000x reference)
#include <cuda_runtime.h>
#include <math.h>

// ---------------------------------------------------------------------------
// AFEModule: fft2(ortho) -> fftshift -> center-mag MLP -> aniso 7x7 kernel ->
// zero-pad conv of shifted spectrum -> 256x256 channel mix -> ifftshift ->
// ifft2(ortho).real + x
//
// Inputs (metadata order): x(8,256,128,128) f32, w1(49,32), b1(32),
//                          w2(32,3), b2(3), wr(256,256)
// Output: (8,256,128,128) f32
// ---------------------------------------------------------------------------

#define NB    8
#define NC    256
#define NIMG  2048          // NB*NC
#define HW    128
#define NPIX  16384         // 128*128
#define LDS_  129           // smem row stride for FFT planes
#define PLANE 16512         // 128*129

#define FFT_SMEM ((2*PLANE + 128) * 4)   // re + im + twiddle tables

#define CP    134           // conv padded rows (128 + 2*3)
#define CPS   136           // conv padded row stride
#define CONV_SMEM (2*CP*CPS*4)

// Scratch (device globals; allocation-free contract).
__device__ __align__(256) float2 g_xf  [NIMG * (size_t)NPIX]; // spectra (shifted); reused as GEMM output
__device__ __align__(256) float2 g_filt[NIMG * (size_t)NPIX]; // conv output (shifted)
__device__ float g_kern[NB * 49];

__device__ __forceinline__ int brev7(int v) { return (int)(__brev((unsigned)v) >> 25); }

// ---------------------------------------------------------------------------
// One 1-D DIF radix-2 FFT pass over all 128 lines of the smem plane.
// Natural-order input, bit-reversed output along the transformed axis.
// lineFast selects the thread->(line,butterfly) mapping for bank friendliness.
// ---------------------------------------------------------------------------
__device__ void fft_pass(float* sre, float* sim,
                         const float* twr, const float* twi,
                         int lineStride, int elemStride, bool lineFast)
{
    #pragma unroll 1
    for (int s = 6; s >= 0; --s) {
        const int h = 1 << s;
        for (int u = threadIdx.x; u < 8192; u += blockDim.x) {
            int line, t;
            if (lineFast) { line = u & 127; t = u >> 7; }
            else          { line = u >> 6;  t = u & 63; }
            const int j    = t & (h - 1);
            const int base = ((t >> s) << (s + 1)) | j;
            const int i0 = line * lineStride + base * elemStride;
            const int i1 = i0 + h * elemStride;
            float ar = sre[i0], ai = sim[i0];
            float br = sre[i1], bi = sim[i1];
            float dr = ar - br, di = ai - bi;
            sre[i0] = ar + br; sim[i0] = ai + bi;
            const int m = j << (6 - s);
            float wr = twr[m], wi = twi[m];
            sre[i1] = dr * wr - di * wi;
            sim[i1] = dr * wi + di * wr;
        }
        __syncthreads();
    }
}

// ---------------------------------------------------------------------------
// Forward FFT2 (ortho) + fftshift: x -> g_xf (shifted layout)
// ---------------------------------------------------------------------------
__global__ void k_fft_fwd(const float* __restrict__ x)
{
    extern __shared__ float sm[];
    float* sre = sm;
    float* sim = sm + PLANE;
    float* twr = sm + 2*PLANE;
    float* twi = twr + 64;

    const int img = blockIdx.x;
    const float* src = x + (size_t)img * NPIX;

    for (int t = threadIdx.x; t < 64; t += blockDim.x) {
        float sv, cv;
        sincosf(-6.283185307179586f * (float)t / 128.0f, &sv, &cv);
        twr[t] = cv; twi[t] = sv;
    }
    for (int i = threadIdx.x; i < NPIX; i += blockDim.x) {
        int y = i >> 7, xx = i & 127;
        sre[y*LDS_ + xx] = src[i];
        sim[y*LDS_ + xx] = 0.0f;
    }
    __syncthreads();

    fft_pass(sre, sim, twr, twi, LDS_, 1, false);   // rows (along x)
    fft_pass(sre, sim, twr, twi, 1, LDS_, true);    // cols (along y)

    float2* dst = g_xf + (size_t)img * NPIX;
    const float sc = 1.0f / 128.0f;                 // ortho: 1/sqrt(128*128)
    for (int i = threadIdx.x; i < NPIX; i += blockDim.x) {
        int u = i >> 7, v = i & 127;
        int o = brev7(u)*LDS_ + brev7(v);
        float re = sre[o] * sc;
        float imv = sim[o] * sc;
        dst[((u+64)&127)*128 + ((v+64)&127)] = make_float2(re, imv);
    }
}

// ---------------------------------------------------------------------------
// Head: center 7x7 magnitude mean over channels -> MLP -> aniso kernel.
// One block per batch, 256 threads (one per channel for the reduction).
// ---------------------------------------------------------------------------
__global__ void k_head(const float* __restrict__ w1, const float* __restrict__ b1,
                       const float* __restrict__ w2, const float* __restrict__ b2)
{
    __shared__ float red[256];
    __shared__ float center[49];
    __shared__ float hid[32];
    __shared__ float par[3];
    __shared__ float kk[50];

    const int b = blockIdx.x;
    const int tid = threadIdx.x;
    const float2* base = g_xf + ((size_t)b * NC + tid) * NPIX;

    for (int p = 0; p < 49; ++p) {
        int h = 61 + p / 7;      // 64 - 3 .. 64 + 3 (shifted layout)
        int w = 61 + p % 7;
        float2 v = base[h*128 + w];
        red[tid] = sqrtf(v.x*v.x + v.y*v.y);
        __syncthreads();
        for (int st = 128; st > 0; st >>= 1) {
            if (tid < st) red[tid] += red[tid + st];
            __syncthreads();
        }
        if (tid == 0) center[p] = red[0] * (1.0f / 256.0f);
        __syncthreads();
    }

    if (tid < 32) {
        float acc = b1[tid];
        for (int p = 0; p < 49; ++p) acc += center[p] * w1[p*32 + tid];
        hid[tid] = fmaxf(acc, 0.0f);
    }
    __syncthreads();
    if (tid < 3) {
        float acc = b2[tid];
        for (int j = 0; j < 32; ++j) acc += hid[j] * w2[j*3 + tid];
        par[tid] = acc;
    }
    __syncthreads();
    if (tid < 49) {
        float theta = atan2f(par[0], par[1]) * 0.5f + 1.5707963267948966f;
        float lam1  = expf(par[2]);
        float lam2  = 1.0f / (lam1 + 1e-8f);
        float ct, st;
        sincosf(theta, &st, &ct);
        float yy = (float)(tid / 7) - 3.0f;
        float xx = (float)(tid % 7) - 3.0f;
        float xr =  xx*ct + yy*st;
        float yr = -xx*st + yy*ct;
        kk[tid] = expf(-(xr*xr / (2.0f*lam1*lam1) + yr*yr / (2.0f*lam2*lam2)));
    }
    __syncthreads();
    if (tid == 0) {
        float s = 0.0f;
        for (int i = 0; i < 49; ++i) s += kk[i];
        kk[49] = s + 1e-8f;
    }
    __syncthreads();
    if (tid < 49) g_kern[b*49 + tid] = kk[tid] / kk[49];
}

// ---------------------------------------------------------------------------
// 7x7 zero-padded cross-correlation of the shifted spectrum (re & im planes).
// One block per image; padded float2 tile in smem.
// ---------------------------------------------------------------------------
__global__ void k_conv()
{
    extern __shared__ float sm[];
    float* sre = sm;
    float* sim = sm + CP*CPS;
    __shared__ float kk[49];

    const int img = blockIdx.x;
    const int b   = img >> 8;

    if (threadIdx.x < 49) kk[threadIdx.x] = g_kern[b*49 + threadIdx.x];
    for (int i = threadIdx.x; i < 2*CP*CPS; i += blockDim.x) sm[i] = 0.0f;
    __syncthreads();

    const float2* src = g_xf + (size_t)img * NPIX;
    for (int i = threadIdx.x; i < NPIX; i += blockDim.x) {
        int y = i >> 7, x = i & 127;
        float2 v = src[i];
        sre[(y+3)*CPS + (x+3)] = v.x;
        sim[(y+3)*CPS + (x+3)] = v.y;
    }
    __syncthreads();

    float2* dst = g_filt + (size_t)img * NPIX;
    for (int i = threadIdx.x; i < NPIX; i += blockDim.x) {
        int y = i >> 7, x = i & 127;
        float ar = 0.0f, ai = 0.0f;
        #pragma unroll
        for (int dy = 0; dy < 7; ++dy) {
            #pragma unroll
            for (int dx = 0; dx < 7; ++dx) {
                float w = kk[dy*7 + dx];
                int o = (y+dy)*CPS + (x+dx);
                ar = fmaf(w, sre[o], ar);
                ai = fmaf(w, sim[o], ai);
            }
        }
        dst[i] = make_float2(ar, ai);
    }
}

// ---------------------------------------------------------------------------
// Channel mix: per batch O[o,p] = sum_c wr[o,c] * F[c,p]  (float2 elements).
// 64x64 tile per block, 4x4 float2 accumulators per thread, K chunks of 16.
// ---------------------------------------------------------------------------
__global__ void k_gemm(const float* __restrict__ wr)
{
    __shared__ float  ws[64][17];     // [o_local][k]   (padded)
    __shared__ float2 fs[16][64];     // [k][p_local]

    const int pBase = blockIdx.x * 64;
    const int oBase = blockIdx.y * 64;
    const int b     = blockIdx.z;
    const int tid   = threadIdx.x;
    const int tx    = tid & 15;       // p group
    const int ty    = tid >> 4;       // o group

    const float2* F = g_filt + (size_t)b * NC * NPIX;

    float2 acc[4][4];
    #pragma unroll
    for (int i = 0; i < 4; ++i)
        #pragma unroll
        for (int j = 0; j < 4; ++j) acc[i][j] = make_float2(0.0f, 0.0f);

    for (int k0 = 0; k0 < NC; k0 += 16) {
        for (int idx = tid; idx < 1024; idx += 256) {
            int o_l = idx >> 4, k = idx & 15;
            ws[o_l][k] = wr[(size_t)(oBase + o_l) * NC + k0 + k];
        }
        for (int idx = tid; idx < 1024; idx += 256) {
            int k = idx >> 6, p_l = idx & 63;
            fs[k][p_l] = F[(size_t)(k0 + k) * NPIX + pBase + p_l];
        }
        __syncthreads();

        #pragma unroll
        for (int k = 0; k < 16; ++k) {
            float  a[4];
            float2 fv[4];
            #pragma unroll
            for (int i = 0; i < 4; ++i) a[i]  = ws[ty + i*16][k];
            #pragma unroll
            for (int j = 0; j < 4; ++j) fv[j] = fs[k][tx + j*16];
            #pragma unroll
            for (int i = 0; i < 4; ++i)
                #pragma unroll
                for (int j = 0; j < 4; ++j) {
                    acc[i][j].x = fmaf(a[i], fv[j].x, acc[i][j].x);
                    acc[i][j].y = fmaf(a[i], fv[j].y, acc[i][j].y);
                }
        }
        __syncthreads();
    }

    float2* O = g_xf + (size_t)b * NC * NPIX;
    #pragma unroll
    for (int i = 0; i < 4; ++i) {
        int o = oBase + ty + i*16;
        #pragma unroll
        for (int j = 0; j < 4; ++j) {
            int p = pBase + tx + j*16;
            O[(size_t)o * NPIX + p] = acc[i][j];
        }
    }
}

// ---------------------------------------------------------------------------
// Inverse FFT2 (ortho) with ifftshift folded into the load; fused ".real + x".
// ---------------------------------------------------------------------------
__global__ void k_ifft(const float* __restrict__ x, float* __restrict__ out)
{
    extern __shared__ float sm[];
    float* sre = sm;
    float* sim = sm + PLANE;
    float* twr = sm + 2*PLANE;
    float* twi = twr + 64;

    const int img = blockIdx.x;
    const float2* src = g_xf + (size_t)img * NPIX;

    for (int t = threadIdx.x; t < 64; t += blockDim.x) {
        float sv, cv;
        sincosf(6.283185307179586f * (float)t / 128.0f, &sv, &cv);
        twr[t] = cv; twi[t] = sv;
    }
    for (int i = threadIdx.x; i < NPIX; i += blockDim.x) {
        int y = i >> 7, xx = i & 127;
        float2 v = src[((y+64)&127)*128 + ((xx+64)&127)];   // ifftshift
        sre[y*LDS_ + xx] = v.x;
        sim[y*LDS_ + xx] = v.y;
    }
    __syncthreads();

    fft_pass(sre, sim, twr, twi, LDS_, 1, false);
    fft_pass(sre, sim, twr, twi, 1, LDS_, true);

    const float* xin = x + (size_t)img * NPIX;
    float* dst = out + (size_t)img * NPIX;
    const float sc = 1.0f / 128.0f;
    for (int i = threadIdx.x; i < NPIX; i += blockDim.x) {
        int u = i >> 7, v = i & 127;
        float re = sre[brev7(u)*LDS_ + brev7(v)];
        dst[i] = re * sc + xin[i];
    }
}

// ---------------------------------------------------------------------------
extern "C" void kernel_launch(void* const* d_in, const int* in_sizes, int n_in,
                              void* d_out, int out_size)
{
    (void)in_sizes; (void)n_in; (void)out_size;
    const float* x  = (const float*)d_in[0];
    const float* w1 = (const float*)d_in[1];
    const float* b1 = (const float*)d_in[2];
    const float* w2 = (const float*)d_in[3];
    const float* b2 = (const float*)d_in[4];
    const float* wr = (const float*)d_in[5];
    float* out = (float*)d_out;

    cudaFuncSetAttribute(k_fft_fwd, cudaFuncAttributeMaxDynamicSharedMemorySize, FFT_SMEM);
    cudaFuncSetAttribute(k_ifft,    cudaFuncAttributeMaxDynamicSharedMemorySize, FFT_SMEM);
    cudaFuncSetAttribute(k_conv,    cudaFuncAttributeMaxDynamicSharedMemorySize, CONV_SMEM);

    k_fft_fwd<<<NIMG, 512, FFT_SMEM>>>(x);
    k_head<<<NB, 256>>>(w1, b1, w2, b2);
    k_conv<<<NIMG, 256, CONV_SMEM>>>();
    k_gemm<<<dim3(NPIX/64, NC/64, NB), 256>>>(wr);
    k_ifft<<<NIMG, 512, FFT_SMEM>>>(x, out);
}

// round 4
// speedup vs baseline: 1.3652x; 1.3652x over previous
#include <cuda_runtime.h>
#include <math.h>

// ---------------------------------------------------------------------------
// AFEModule: fft2(ortho) -> fftshift -> center-mag MLP -> aniso 7x7 kernel ->
// zero-pad conv of shifted spectrum -> 256x256 channel mix -> ifftshift ->
// ifft2(ortho).real + x
// ---------------------------------------------------------------------------

#define NB    8
#define NC    256
#define NIMG  2048
#define HW    128
#define NPIX  16384
#define LDS_  129
#define PLANE 16512

#define FFT_SMEM ((2*PLANE + 128) * 4)

#define CP    134
#define CPS   136
#define CONV_SMEM (2*CP*CPS*4)

__device__ __align__(256) float2 g_xf  [NIMG * (size_t)NPIX]; // spectra (shifted); reused as GEMM out
__device__ __align__(256) float2 g_filt[NIMG * (size_t)NPIX]; // conv output (shifted)
__device__ float g_kern[NB * 49];

__device__ __forceinline__ int brev7(int v) { return (int)(__brev((unsigned)v) >> 25); }

// ---------------------------------------------------------------------------
// 1-D DIF FFT over all 128 lines, radix-2 stages fused in pairs:
// exchange rounds (6,5), (4,3), (2,1), then single stage 0.
// Natural-order in, bit-reversed out along transformed axis.
// ---------------------------------------------------------------------------
__device__ void fft_pass(float* sre, float* sim,
                         const float* twr, const float* twi,
                         int lineStride, int elemStride, bool lineFast)
{
    #pragma unroll 1
    for (int s = 6; s >= 2; s -= 2) {
        const int q = 1 << (s - 1);
        for (int u = threadIdx.x; u < 4096; u += blockDim.x) {
            int line, t;
            if (lineFast) { line = u & 127; t = u >> 7; }
            else          { line = u >> 5;  t = u & 31; }
            const int j    = t & (q - 1);
            const int base = ((t >> (s - 1)) << (s + 1)) | j;
            const int o0   = line * lineStride + base * elemStride;
            const int oq   = q * elemStride;

            float Ar = sre[o0],        Ai = sim[o0];
            float Br = sre[o0 + oq],   Bi = sim[o0 + oq];
            float Cr = sre[o0 + 2*oq], Ci = sim[o0 + 2*oq];
            float Dr = sre[o0 + 3*oq], Di = sim[o0 + 3*oq];

            const float w1r = twr[j << (6 - s)],       w1i = twi[j << (6 - s)];
            const float w2r = twr[(j + q) << (6 - s)], w2i = twi[(j + q) << (6 - s)];
            const float w3r = twr[j << (7 - s)],       w3i = twi[j << (7 - s)];

            // stage s: pairs (A,C) [dist 2q] and (B,D)
            float t0r = Ar + Cr, t0i = Ai + Ci;
            float d0r = Ar - Cr, d0i = Ai - Ci;
            float Cpr = d0r*w1r - d0i*w1i, Cpi = d0r*w1i + d0i*w1r;
            float t1r = Br + Dr, t1i = Bi + Di;
            float d1r = Br - Dr, d1i = Bi - Di;
            float Dpr = d1r*w2r - d1i*w2i, Dpi = d1r*w2i + d1i*w2r;

            // stage s-1: pairs (A',B') [dist q] and (C',D')
            sre[o0]        = t0r + t1r;  sim[o0]        = t0i + t1i;
            float e1r = t0r - t1r, e1i = t0i - t1i;
            sre[o0 + oq]   = e1r*w3r - e1i*w3i;
            sim[o0 + oq]   = e1r*w3i + e1i*w3r;
            sre[o0 + 2*oq] = Cpr + Dpr;  sim[o0 + 2*oq] = Cpi + Dpi;
            float e3r = Cpr - Dpr, e3i = Cpi - Dpi;
            sre[o0 + 3*oq] = e3r*w3r - e3i*w3i;
            sim[o0 + 3*oq] = e3r*w3i + e3i*w3r;
        }
        __syncthreads();
    }
    // final stage s=0 (no twiddle)
    for (int u = threadIdx.x; u < 8192; u += blockDim.x) {
        int line, k;
        if (lineFast) { line = u & 127; k = u >> 7; }
        else          { line = u >> 6;  k = u & 63; }
        const int o0 = line * lineStride + (2*k) * elemStride;
        const int o1 = o0 + elemStride;
        float ar = sre[o0], ai = sim[o0], br = sre[o1], bi = sim[o1];
        sre[o0] = ar + br; sim[o0] = ai + bi;
        sre[o1] = ar - br; sim[o1] = ai - bi;
    }
    __syncthreads();
}

// ---------------------------------------------------------------------------
__global__ void k_fft_fwd(const float* __restrict__ x)
{
    extern __shared__ float sm[];
    float* sre = sm;
    float* sim = sm + PLANE;
    float* twr = sm + 2*PLANE;
    float* twi = twr + 64;

    const int img = blockIdx.x;
    const float* src = x + (size_t)img * NPIX;

    for (int t = threadIdx.x; t < 64; t += blockDim.x) {
        float sv, cv;
        sincosf(-6.283185307179586f * (float)t / 128.0f, &sv, &cv);
        twr[t] = cv; twi[t] = sv;
    }
    for (int i = threadIdx.x; i < NPIX; i += blockDim.x) {
        int y = i >> 7, xx = i & 127;
        sre[y*LDS_ + xx] = src[i];
        sim[y*LDS_ + xx] = 0.0f;
    }
    __syncthreads();

    fft_pass(sre, sim, twr, twi, LDS_, 1, false);   // rows
    fft_pass(sre, sim, twr, twi, 1, LDS_, true);    // cols

    float2* dst = g_xf + (size_t)img * NPIX;
    const float sc = 1.0f / 128.0f;
    for (int i = threadIdx.x; i < NPIX; i += blockDim.x) {
        int u = i >> 7, v = i & 127;
        int o = brev7(u)*LDS_ + brev7(v);
        dst[((u+64)&127)*128 + ((v+64)&127)] = make_float2(sre[o]*sc, sim[o]*sc);
    }
}

// ---------------------------------------------------------------------------
__global__ void k_head(const float* __restrict__ w1, const float* __restrict__ b1,
                       const float* __restrict__ w2, const float* __restrict__ b2)
{
    __shared__ float red[256];
    __shared__ float center[49];
    __shared__ float hid[32];
    __shared__ float par[3];
    __shared__ float kk[50];

    const int b = blockIdx.x;
    const int tid = threadIdx.x;
    const float2* base = g_xf + ((size_t)b * NC + tid) * NPIX;

    for (int p = 0; p < 49; ++p) {
        int h = 61 + p / 7;
        int w = 61 + p % 7;
        float2 v = base[h*128 + w];
        red[tid] = sqrtf(v.x*v.x + v.y*v.y);
        __syncthreads();
        for (int st = 128; st > 0; st >>= 1) {
            if (tid < st) red[tid] += red[tid + st];
            __syncthreads();
        }
        if (tid == 0) center[p] = red[0] * (1.0f / 256.0f);
        __syncthreads();
    }

    if (tid < 32) {
        float acc = b1[tid];
        for (int p = 0; p < 49; ++p) acc += center[p] * w1[p*32 + tid];
        hid[tid] = fmaxf(acc, 0.0f);
    }
    __syncthreads();
    if (tid < 3) {
        float acc = b2[tid];
        for (int j = 0; j < 32; ++j) acc += hid[j] * w2[j*3 + tid];
        par[tid] = acc;
    }
    __syncthreads();
    if (tid < 49) {
        float theta = atan2f(par[0], par[1]) * 0.5f + 1.5707963267948966f;
        float lam1  = expf(par[2]);
        float lam2  = 1.0f / (lam1 + 1e-8f);
        float ct, st;
        sincosf(theta, &st, &ct);
        float yy = (float)(tid / 7) - 3.0f;
        float xx = (float)(tid % 7) - 3.0f;
        float xr =  xx*ct + yy*st;
        float yr = -xx*st + yy*ct;
        kk[tid] = expf(-(xr*xr / (2.0f*lam1*lam1) + yr*yr / (2.0f*lam2*lam2)));
    }
    __syncthreads();
    if (tid == 0) {
        float s = 0.0f;
        for (int i = 0; i < 49; ++i) s += kk[i];
        kk[49] = s + 1e-8f;
    }
    __syncthreads();
    if (tid < 49) g_kern[b*49 + tid] = kk[tid] / kk[49];
}

// ---------------------------------------------------------------------------
// 7x7 zero-pad conv, 8-wide register strips, float4 window loads.
// ---------------------------------------------------------------------------
__global__ void k_conv()
{
    extern __shared__ float sm[];
    float* sre = sm;
    float* sim = sm + CP*CPS;
    __shared__ float kk[49];

    const int img = blockIdx.x;
    const int b   = img >> 8;

    if (threadIdx.x < 49) kk[threadIdx.x] = g_kern[b*49 + threadIdx.x];
    for (int i = threadIdx.x; i < 2*CP*CPS; i += blockDim.x) sm[i] = 0.0f;
    __syncthreads();

    const float2* src = g_xf + (size_t)img * NPIX;
    for (int i = threadIdx.x; i < NPIX; i += blockDim.x) {
        int y = i >> 7, x = i & 127;
        float2 v = src[i];
        sre[(y+3)*CPS + (x+3)] = v.x;
        sim[(y+3)*CPS + (x+3)] = v.y;
    }
    __syncthreads();

    float2* dst = g_filt + (size_t)img * NPIX;
    for (int st = threadIdx.x; st < 2048; st += blockDim.x) {
        const int y  = st >> 4;
        const int x0 = (st & 15) << 3;
        float accr[8] = {0,0,0,0,0,0,0,0};
        float acci[8] = {0,0,0,0,0,0,0,0};
        #pragma unroll
        for (int dy = 0; dy < 7; ++dy) {
            const float* pr = &sre[(y+dy)*CPS + x0];
            const float* pi = &sim[(y+dy)*CPS + x0];
            float re[16], im[16];
            *(float4*)&re[0]  = *(const float4*)&pr[0];
            *(float4*)&re[4]  = *(const float4*)&pr[4];
            *(float4*)&re[8]  = *(const float4*)&pr[8];
            *(float4*)&re[12] = *(const float4*)&pr[12];
            *(float4*)&im[0]  = *(const float4*)&pi[0];
            *(float4*)&im[4]  = *(const float4*)&pi[4];
            *(float4*)&im[8]  = *(const float4*)&pi[8];
            *(float4*)&im[12] = *(const float4*)&pi[12];
            #pragma unroll
            for (int dx = 0; dx < 7; ++dx) {
                float w = kk[dy*7 + dx];
                #pragma unroll
                for (int p = 0; p < 8; ++p) {
                    accr[p] = fmaf(w, re[dx+p], accr[p]);
                    acci[p] = fmaf(w, im[dx+p], acci[p]);
                }
            }
        }
        float2* d = dst + y*128 + x0;
        #pragma unroll
        for (int p = 0; p < 8; ++p) d[p] = make_float2(accr[p], acci[p]);
    }
}

// ---------------------------------------------------------------------------
// Channel mix GEMM: per batch C[256, 32768] = wr[256,256] @ Ffloat[256,32768].
// 128x128 tile, 256 threads, 8x8 micro-tile, float4 smem I/O.
// ---------------------------------------------------------------------------
#define BM 128
#define BN 128
#define BK 16

__global__ void __launch_bounds__(256, 2) k_gemm(const float* __restrict__ wr)
{
    __shared__ float As[BK][BM];
    __shared__ float Bs[BK][BN];

    const int b     = blockIdx.z;
    const int oBase = blockIdx.y * BM;
    const int pBase = blockIdx.x * BN;
    const int tid   = threadIdx.x;
    const int tx    = tid & 15;
    const int ty    = tid >> 4;

    const float* F = (const float*)(g_filt + (size_t)b * NC * NPIX); // [c][32768]
    float*       O = (float*)(g_xf   + (size_t)b * NC * NPIX);

    const int arow  = tid >> 2;
    const int acol4 = (tid & 3) * 4;
    const int brow  = tid >> 5;
    const int bcol4 = (tid & 31) * 4;

    float acc[8][8];
    #pragma unroll
    for (int i = 0; i < 8; ++i)
        #pragma unroll
        for (int j = 0; j < 8; ++j) acc[i][j] = 0.0f;

    for (int k0 = 0; k0 < NC; k0 += BK) {
        #pragma unroll
        for (int r = 0; r < 2; ++r) {
            int row = arow + r*64;
            float4 v = *(const float4*)&wr[(size_t)(oBase + row)*NC + k0 + acol4];
            As[acol4+0][row] = v.x;
            As[acol4+1][row] = v.y;
            As[acol4+2][row] = v.z;
            As[acol4+3][row] = v.w;
        }
        #pragma unroll
        for (int r = 0; r < 2; ++r) {
            int row = brow + r*8;
            *(float4*)&Bs[row][bcol4] =
                *(const float4*)&F[(size_t)(k0+row)*32768 + pBase + bcol4];
        }
        __syncthreads();

        #pragma unroll
        for (int k = 0; k < BK; ++k) {
            float ar[8], br[8];
            *(float4*)&ar[0] = *(float4*)&As[k][ty*8];
            *(float4*)&ar[4] = *(float4*)&As[k][ty*8 + 4];
            *(float4*)&br[0] = *(float4*)&Bs[k][tx*8];
            *(float4*)&br[4] = *(float4*)&Bs[k][tx*8 + 4];
            #pragma unroll
            for (int i = 0; i < 8; ++i)
                #pragma unroll
                for (int j = 0; j < 8; ++j)
                    acc[i][j] = fmaf(ar[i], br[j], acc[i][j]);
        }
        __syncthreads();
    }

    #pragma unroll
    for (int i = 0; i < 8; ++i) {
        size_t o = (size_t)(oBase + ty*8 + i);
        #pragma unroll
        for (int j = 0; j < 8; j += 4)
            *(float4*)&O[o*32768 + pBase + tx*8 + j] = *(float4*)&acc[i][j];
    }
}

// ---------------------------------------------------------------------------
__global__ void k_ifft(const float* __restrict__ x, float* __restrict__ out)
{
    extern __shared__ float sm[];
    float* sre = sm;
    float* sim = sm + PLANE;
    float* twr = sm + 2*PLANE;
    float* twi = twr + 64;

    const int img = blockIdx.x;
    const float2* src = g_xf + (size_t)img * NPIX;

    for (int t = threadIdx.x; t < 64; t += blockDim.x) {
        float sv, cv;
        sincosf(6.283185307179586f * (float)t / 128.0f, &sv, &cv);
        twr[t] = cv; twi[t] = sv;
    }
    for (int i = threadIdx.x; i < NPIX; i += blockDim.x) {
        int y = i >> 7, xx = i & 127;
        float2 v = src[((y+64)&127)*128 + ((xx+64)&127)];
        sre[y*LDS_ + xx] = v.x;
        sim[y*LDS_ + xx] = v.y;
    }
    __syncthreads();

    fft_pass(sre, sim, twr, twi, LDS_, 1, false);
    fft_pass(sre, sim, twr, twi, 1, LDS_, true);

    const float* xin = x + (size_t)img * NPIX;
    float* dst = out + (size_t)img * NPIX;
    const float sc = 1.0f / 128.0f;
    for (int i = threadIdx.x; i < NPIX; i += blockDim.x) {
        int u = i >> 7, v = i & 127;
        dst[i] = sre[brev7(u)*LDS_ + brev7(v)] * sc + xin[i];
    }
}

// ---------------------------------------------------------------------------
extern "C" void kernel_launch(void* const* d_in, const int* in_sizes, int n_in,
                              void* d_out, int out_size)
{
    (void)in_sizes; (void)n_in; (void)out_size;
    const float* x  = (const float*)d_in[0];
    const float* w1 = (const float*)d_in[1];
    const float* b1 = (const float*)d_in[2];
    const float* w2 = (const float*)d_in[3];
    const float* b2 = (const float*)d_in[4];
    const float* wr = (const float*)d_in[5];
    float* out = (float*)d_out;

    cudaFuncSetAttribute(k_fft_fwd, cudaFuncAttributeMaxDynamicSharedMemorySize, FFT_SMEM);
    cudaFuncSetAttribute(k_ifft,    cudaFuncAttributeMaxDynamicSharedMemorySize, FFT_SMEM);
    cudaFuncSetAttribute(k_conv,    cudaFuncAttributeMaxDynamicSharedMemorySize, CONV_SMEM);

    k_fft_fwd<<<NIMG, 512, FFT_SMEM>>>(x);
    k_head<<<NB, 256>>>(w1, b1, w2, b2);
    k_conv<<<NIMG, 512, CONV_SMEM>>>();
    k_gemm<<<dim3(32768/BN, NC/BM, NB), 256>>>(wr);
    k_ifft<<<NIMG, 512, FFT_SMEM>>>(x, out);
}

// round 5
// speedup vs baseline: 1.8487x; 1.3542x over previous
#include <cuda_runtime.h>
#include <cuda_bf16.h>
#include <math.h>

// ---------------------------------------------------------------------------
// AFEModule: fft2(ortho) -> fftshift -> center-mag MLP -> aniso 7x7 kernel ->
// zero-pad conv of shifted spectrum -> 256x256 channel mix -> ifftshift ->
// ifft2(ortho).real + x
// ---------------------------------------------------------------------------

#define NB    8
#define NC    256
#define NIMG  2048
#define HW    128
#define NPIX  16384
#define LDS_  129
#define PLANE 16512

#define FFT_SMEM ((2*PLANE + 128) * 4)

#define CP    134
#define CPS   136
#define CONV_SMEM (2*CP*CPS*4)

// Scratch (device globals; allocation-free contract).
__device__ __align__(256) float2 g_xf[NIMG * (size_t)NPIX];            // spectra (shifted); reused as GEMM out
__device__ __align__(256) __nv_bfloat16 g_fhi[NIMG * (size_t)NPIX * 2]; // conv out hi (re,im interleaved)
__device__ __align__(256) __nv_bfloat16 g_flo[NIMG * (size_t)NPIX * 2]; // conv out lo
__device__ __align__(16)  __nv_bfloat16 g_wrhi[NC * NC];
__device__ __align__(16)  __nv_bfloat16 g_wrlo[NC * NC];
__device__ float g_kern[NB * 49];

__device__ __forceinline__ int brev7(int v) { return (int)(__brev((unsigned)v) >> 25); }

// ---------------------------------------------------------------------------
// 1-D DIF FFT over all 128 lines, radix-2 stages fused in pairs.
// ---------------------------------------------------------------------------
__device__ void fft_pass(float* sre, float* sim,
                         const float* twr, const float* twi,
                         int lineStride, int elemStride, bool lineFast)
{
    #pragma unroll 1
    for (int s = 6; s >= 2; s -= 2) {
        const int q = 1 << (s - 1);
        for (int u = threadIdx.x; u < 4096; u += blockDim.x) {
            int line, t;
            if (lineFast) { line = u & 127; t = u >> 7; }
            else          { line = u >> 5;  t = u & 31; }
            const int j    = t & (q - 1);
            const int base = ((t >> (s - 1)) << (s + 1)) | j;
            const int o0   = line * lineStride + base * elemStride;
            const int oq   = q * elemStride;

            float Ar = sre[o0],        Ai = sim[o0];
            float Br = sre[o0 + oq],   Bi = sim[o0 + oq];
            float Cr = sre[o0 + 2*oq], Ci = sim[o0 + 2*oq];
            float Dr = sre[o0 + 3*oq], Di = sim[o0 + 3*oq];

            const float w1r = twr[j << (6 - s)],       w1i = twi[j << (6 - s)];
            const float w2r = twr[(j + q) << (6 - s)], w2i = twi[(j + q) << (6 - s)];
            const float w3r = twr[j << (7 - s)],       w3i = twi[j << (7 - s)];

            float t0r = Ar + Cr, t0i = Ai + Ci;
            float d0r = Ar - Cr, d0i = Ai - Ci;
            float Cpr = d0r*w1r - d0i*w1i, Cpi = d0r*w1i + d0i*w1r;
            float t1r = Br + Dr, t1i = Bi + Di;
            float d1r = Br - Dr, d1i = Bi - Di;
            float Dpr = d1r*w2r - d1i*w2i, Dpi = d1r*w2i + d1i*w2r;

            sre[o0]        = t0r + t1r;  sim[o0]        = t0i + t1i;
            float e1r = t0r - t1r, e1i = t0i - t1i;
            sre[o0 + oq]   = e1r*w3r - e1i*w3i;
            sim[o0 + oq]   = e1r*w3i + e1i*w3r;
            sre[o0 + 2*oq] = Cpr + Dpr;  sim[o0 + 2*oq] = Cpi + Dpi;
            float e3r = Cpr - Dpr, e3i = Cpi - Dpi;
            sre[o0 + 3*oq] = e3r*w3r - e3i*w3i;
            sim[o0 + 3*oq] = e3r*w3i + e3i*w3r;
        }
        __syncthreads();
    }
    for (int u = threadIdx.x; u < 8192; u += blockDim.x) {
        int line, k;
        if (lineFast) { line = u & 127; k = u >> 7; }
        else          { line = u >> 6;  k = u & 63; }
        const int o0 = line * lineStride + (2*k) * elemStride;
        const int o1 = o0 + elemStride;
        float ar = sre[o0], ai = sim[o0], br = sre[o1], bi = sim[o1];
        sre[o0] = ar + br; sim[o0] = ai + bi;
        sre[o1] = ar - br; sim[o1] = ai - bi;
    }
    __syncthreads();
}

// ---------------------------------------------------------------------------
__global__ void k_fft_fwd(const float* __restrict__ x)
{
    extern __shared__ float sm[];
    float* sre = sm;
    float* sim = sm + PLANE;
    float* twr = sm + 2*PLANE;
    float* twi = twr + 64;

    const int img = blockIdx.x;
    const float* src = x + (size_t)img * NPIX;

    for (int t = threadIdx.x; t < 64; t += blockDim.x) {
        float sv, cv;
        sincosf(-6.283185307179586f * (float)t / 128.0f, &sv, &cv);
        twr[t] = cv; twi[t] = sv;
    }
    for (int i = threadIdx.x; i < NPIX; i += blockDim.x) {
        int y = i >> 7, xx = i & 127;
        sre[y*LDS_ + xx] = src[i];
        sim[y*LDS_ + xx] = 0.0f;
    }
    __syncthreads();

    fft_pass(sre, sim, twr, twi, LDS_, 1, false);
    fft_pass(sre, sim, twr, twi, 1, LDS_, true);

    float2* dst = g_xf + (size_t)img * NPIX;
    const float sc = 1.0f / 128.0f;
    for (int i = threadIdx.x; i < NPIX; i += blockDim.x) {
        int u = i >> 7, v = i & 127;
        int o = brev7(u)*LDS_ + brev7(v);
        dst[((u+64)&127)*128 + ((v+64)&127)] = make_float2(sre[o]*sc, sim[o]*sc);
    }
}

// ---------------------------------------------------------------------------
__global__ void k_head(const float* __restrict__ w1, const float* __restrict__ b1,
                       const float* __restrict__ w2, const float* __restrict__ b2)
{
    __shared__ float red[256];
    __shared__ float center[49];
    __shared__ float hid[32];
    __shared__ float par[3];
    __shared__ float kk[50];

    const int b = blockIdx.x;
    const int tid = threadIdx.x;
    const float2* base = g_xf + ((size_t)b * NC + tid) * NPIX;

    for (int p = 0; p < 49; ++p) {
        int h = 61 + p / 7;
        int w = 61 + p % 7;
        float2 v = base[h*128 + w];
        red[tid] = sqrtf(v.x*v.x + v.y*v.y);
        __syncthreads();
        for (int st = 128; st > 0; st >>= 1) {
            if (tid < st) red[tid] += red[tid + st];
            __syncthreads();
        }
        if (tid == 0) center[p] = red[0] * (1.0f / 256.0f);
        __syncthreads();
    }

    if (tid < 32) {
        float acc = b1[tid];
        for (int p = 0; p < 49; ++p) acc += center[p] * w1[p*32 + tid];
        hid[tid] = fmaxf(acc, 0.0f);
    }
    __syncthreads();
    if (tid < 3) {
        float acc = b2[tid];
        for (int j = 0; j < 32; ++j) acc += hid[j] * w2[j*3 + tid];
        par[tid] = acc;
    }
    __syncthreads();
    if (tid < 49) {
        float theta = atan2f(par[0], par[1]) * 0.5f + 1.5707963267948966f;
        float lam1  = expf(par[2]);
        float lam2  = 1.0f / (lam1 + 1e-8f);
        float ct, st;
        sincosf(theta, &st, &ct);
        float yy = (float)(tid / 7) - 3.0f;
        float xx = (float)(tid % 7) - 3.0f;
        float xr =  xx*ct + yy*st;
        float yr = -xx*st + yy*ct;
        kk[tid] = expf(-(xr*xr / (2.0f*lam1*lam1) + yr*yr / (2.0f*lam2*lam2)));
    }
    __syncthreads();
    if (tid == 0) {
        float s = 0.0f;
        for (int i = 0; i < 49; ++i) s += kk[i];
        kk[49] = s + 1e-8f;
    }
    __syncthreads();
    if (tid < 49) g_kern[b*49 + tid] = kk[tid] / kk[49];
}

// ---------------------------------------------------------------------------
// wr split into bf16 hi/lo.
// ---------------------------------------------------------------------------
__global__ void k_prep(const float* __restrict__ wr)
{
    int i = blockIdx.x * 256 + threadIdx.x;
    float v = wr[i];
    __nv_bfloat16 h = __float2bfloat16(v);
    g_wrhi[i] = h;
    g_wrlo[i] = __float2bfloat16(v - __bfloat162float(h));
}

// ---------------------------------------------------------------------------
// 7x7 zero-pad conv; outputs bf16 hi/lo planes (re,im interleaved).
// ---------------------------------------------------------------------------
__global__ void k_conv()
{
    extern __shared__ float sm[];
    float* sre = sm;
    float* sim = sm + CP*CPS;
    __shared__ float kk[49];

    const int img = blockIdx.x;
    const int b   = img >> 8;

    if (threadIdx.x < 49) kk[threadIdx.x] = g_kern[b*49 + threadIdx.x];
    for (int i = threadIdx.x; i < 2*CP*CPS; i += blockDim.x) sm[i] = 0.0f;
    __syncthreads();

    const float2* src = g_xf + (size_t)img * NPIX;
    for (int i = threadIdx.x; i < NPIX; i += blockDim.x) {
        int y = i >> 7, x = i & 127;
        float2 v = src[i];
        sre[(y+3)*CPS + (x+3)] = v.x;
        sim[(y+3)*CPS + (x+3)] = v.y;
    }
    __syncthreads();

    __nv_bfloat162* dh = (__nv_bfloat162*)(g_fhi + (size_t)img * NPIX * 2);
    __nv_bfloat162* dl = (__nv_bfloat162*)(g_flo + (size_t)img * NPIX * 2);
    for (int st = threadIdx.x; st < 2048; st += blockDim.x) {
        const int y  = st >> 4;
        const int x0 = (st & 15) << 3;
        float accr[8] = {0,0,0,0,0,0,0,0};
        float acci[8] = {0,0,0,0,0,0,0,0};
        #pragma unroll
        for (int dy = 0; dy < 7; ++dy) {
            const float* pr = &sre[(y+dy)*CPS + x0];
            const float* pi = &sim[(y+dy)*CPS + x0];
            float re[16], im[16];
            *(float4*)&re[0]  = *(const float4*)&pr[0];
            *(float4*)&re[4]  = *(const float4*)&pr[4];
            *(float4*)&re[8]  = *(const float4*)&pr[8];
            *(float4*)&re[12] = *(const float4*)&pr[12];
            *(float4*)&im[0]  = *(const float4*)&pi[0];
            *(float4*)&im[4]  = *(const float4*)&pi[4];
            *(float4*)&im[8]  = *(const float4*)&pi[8];
            *(float4*)&im[12] = *(const float4*)&pi[12];
            #pragma unroll
            for (int dx = 0; dx < 7; ++dx) {
                float w = kk[dy*7 + dx];
                #pragma unroll
                for (int p = 0; p < 8; ++p) {
                    accr[p] = fmaf(w, re[dx+p], accr[p]);
                    acci[p] = fmaf(w, im[dx+p], acci[p]);
                }
            }
        }
        const int o = y*128 + x0;
        #pragma unroll
        for (int p = 0; p < 8; ++p) {
            __nv_bfloat16 hr = __float2bfloat16(accr[p]);
            __nv_bfloat16 hi = __float2bfloat16(acci[p]);
            dh[o + p] = __nv_bfloat162(hr, hi);
            __nv_bfloat16 lr = __float2bfloat16(accr[p] - __bfloat162float(hr));
            __nv_bfloat16 li = __float2bfloat16(acci[p] - __bfloat162float(hi));
            dl[o + p] = __nv_bfloat162(lr, li);
        }
    }
}

// ---------------------------------------------------------------------------
// Tensor-core channel-mix GEMM (bf16x3): per batch
//   C[o, p] = sum_k wr[o,k] * F[k,p]   with A,B split into bf16 hi+lo:
//   C = Ah*Bh + Ah*Bl + Al*Bh
// Block: 128(o) x 128(p), K-tile 32. 8 warps: 4(o) x 2(p), each 32o x 64p.
// ---------------------------------------------------------------------------
#define SWS 40    // wr smem stride (bf16): 80 B -> conflict-free ldmatrix
#define SFS 136   // F  smem stride (bf16): 272 B -> conflict-free ldmatrix

__device__ __forceinline__ void ldsm_x4(unsigned& r0, unsigned& r1, unsigned& r2, unsigned& r3,
                                        unsigned addr)
{
    asm volatile("ldmatrix.sync.aligned.m8n8.x4.shared.b16 {%0,%1,%2,%3}, [%4];"
                 : "=r"(r0), "=r"(r1), "=r"(r2), "=r"(r3) : "r"(addr));
}
__device__ __forceinline__ void ldsm_x4_t(unsigned& r0, unsigned& r1, unsigned& r2, unsigned& r3,
                                          unsigned addr)
{
    asm volatile("ldmatrix.sync.aligned.m8n8.x4.trans.shared.b16 {%0,%1,%2,%3}, [%4];"
                 : "=r"(r0), "=r"(r1), "=r"(r2), "=r"(r3) : "r"(addr));
}
__device__ __forceinline__ void mma16816(float* c, const unsigned* a, const unsigned* b)
{
    asm volatile("mma.sync.aligned.m16n8k16.row.col.f32.bf16.bf16.f32 "
                 "{%0,%1,%2,%3}, {%4,%5,%6,%7}, {%8,%9}, {%0,%1,%2,%3};"
                 : "+f"(c[0]), "+f"(c[1]), "+f"(c[2]), "+f"(c[3])
                 : "r"(a[0]), "r"(a[1]), "r"(a[2]), "r"(a[3]), "r"(b[0]), "r"(b[1]));
}

__global__ void __launch_bounds__(256) k_gemm_tc()
{
    __shared__ __nv_bfloat16 sWh[128*SWS], sWl[128*SWS];
    __shared__ __nv_bfloat16 sFh[32*SFS],  sFl[32*SFS];

    const int b     = blockIdx.z;
    const int oBase = blockIdx.y * 128;
    const int pBase = blockIdx.x * 128;
    const int tid   = threadIdx.x;
    const int lane  = tid & 31;
    const int warp  = tid >> 5;
    const int wo    = warp >> 1;      // 0..3 -> o offset *32
    const int wp    = warp & 1;       // 0..1 -> p offset *64

    const __nv_bfloat16* Fh = g_fhi + (size_t)b * NC * 32768;
    const __nv_bfloat16* Fl = g_flo + (size_t)b * NC * 32768;

    const unsigned swh = (unsigned)__cvta_generic_to_shared(sWh);
    const unsigned swl = (unsigned)__cvta_generic_to_shared(sWl);
    const unsigned sfh = (unsigned)__cvta_generic_to_shared(sFh);
    const unsigned sfl = (unsigned)__cvta_generic_to_shared(sFl);

    float acc[2][8][4];
    #pragma unroll
    for (int m = 0; m < 2; ++m)
        #pragma unroll
        for (int n = 0; n < 8; ++n)
            #pragma unroll
            for (int q = 0; q < 4; ++q) acc[m][n][q] = 0.0f;

    // ldmatrix per-lane offsets (element units)
    const int aRow = lane & 15;              // within m16 tile
    const int aKof = (lane >> 4) << 3;       // k half
    const int bKrow = lane & 15;             // within k16
    const int bPof  = (lane >> 4) << 3;      // p half (tile pair)

    for (int k0 = 0; k0 < NC; k0 += 32) {
        #pragma unroll
        for (int t = 0; t < 2; ++t) {
            int id = tid + t*256;
            int o  = id >> 2, kc = (id & 3) << 3;
            *(uint4*)&sWh[o*SWS + kc] = *(const uint4*)&g_wrhi[(oBase + o)*NC + k0 + kc];
            *(uint4*)&sWl[o*SWS + kc] = *(const uint4*)&g_wrlo[(oBase + o)*NC + k0 + kc];
        }
        #pragma unroll
        for (int t = 0; t < 2; ++t) {
            int id = tid + t*256;
            int k  = id >> 4, pc = (id & 15) << 3;
            *(uint4*)&sFh[k*SFS + pc] = *(const uint4*)&Fh[(size_t)(k0 + k)*32768 + pBase + pc];
            *(uint4*)&sFl[k*SFS + pc] = *(const uint4*)&Fl[(size_t)(k0 + k)*32768 + pBase + pc];
        }
        __syncthreads();

        #pragma unroll
        for (int kk = 0; kk < 32; kk += 16) {
            unsigned ah[2][4], al[2][4];
            #pragma unroll
            for (int mt = 0; mt < 2; ++mt) {
                unsigned off = ((wo*32 + mt*16 + aRow)*SWS + kk + aKof) * 2;
                ldsm_x4(ah[mt][0], ah[mt][1], ah[mt][2], ah[mt][3], swh + off);
                ldsm_x4(al[mt][0], al[mt][1], al[mt][2], al[mt][3], swl + off);
            }
            unsigned bh[8][2], bl[8][2];
            #pragma unroll
            for (int ng = 0; ng < 4; ++ng) {
                unsigned off = ((kk + bKrow)*SFS + wp*64 + ng*16 + bPof) * 2;
                ldsm_x4_t(bh[2*ng][0], bh[2*ng][1], bh[2*ng+1][0], bh[2*ng+1][1], sfh + off);
                ldsm_x4_t(bl[2*ng][0], bl[2*ng][1], bl[2*ng+1][0], bl[2*ng+1][1], sfl + off);
            }
            #pragma unroll
            for (int mt = 0; mt < 2; ++mt)
                #pragma unroll
                for (int nt = 0; nt < 8; ++nt) {
                    mma16816(acc[mt][nt], ah[mt], bh[nt]);
                    mma16816(acc[mt][nt], ah[mt], bl[nt]);
                    mma16816(acc[mt][nt], al[mt], bh[nt]);
                }
        }
        __syncthreads();
    }

    float* O = (float*)(g_xf + (size_t)b * NC * NPIX);
    const int cRow = lane >> 2;
    const int cCol = (lane & 3) << 1;
    #pragma unroll
    for (int mt = 0; mt < 2; ++mt) {
        #pragma unroll
        for (int nt = 0; nt < 8; ++nt) {
            size_t o0 = (size_t)(oBase + wo*32 + mt*16 + cRow);
            size_t p  = (size_t)(pBase + wp*64 + nt*8 + cCol);
            *(float2*)&O[o0*32768 + p]       = make_float2(acc[mt][nt][0], acc[mt][nt][1]);
            *(float2*)&O[(o0+8)*32768 + p]   = make_float2(acc[mt][nt][2], acc[mt][nt][3]);
        }
    }
}

// ---------------------------------------------------------------------------
__global__ void k_ifft(const float* __restrict__ x, float* __restrict__ out)
{
    extern __shared__ float sm[];
    float* sre = sm;
    float* sim = sm + PLANE;
    float* twr = sm + 2*PLANE;
    float* twi = twr + 64;

    const int img = blockIdx.x;
    const float2* src = g_xf + (size_t)img * NPIX;

    for (int t = threadIdx.x; t < 64; t += blockDim.x) {
        float sv, cv;
        sincosf(6.283185307179586f * (float)t / 128.0f, &sv, &cv);
        twr[t] = cv; twi[t] = sv;
    }
    for (int i = threadIdx.x; i < NPIX; i += blockDim.x) {
        int y = i >> 7, xx = i & 127;
        float2 v = src[((y+64)&127)*128 + ((xx+64)&127)];
        sre[y*LDS_ + xx] = v.x;
        sim[y*LDS_ + xx] = v.y;
    }
    __syncthreads();

    fft_pass(sre, sim, twr, twi, LDS_, 1, false);
    fft_pass(sre, sim, twr, twi, 1, LDS_, true);

    const float* xin = x + (size_t)img * NPIX;
    float* dst = out + (size_t)img * NPIX;
    const float sc = 1.0f / 128.0f;
    for (int i = threadIdx.x; i < NPIX; i += blockDim.x) {
        int u = i >> 7, v = i & 127;
        dst[i] = sre[brev7(u)*LDS_ + brev7(v)] * sc + xin[i];
    }
}

// ---------------------------------------------------------------------------
extern "C" void kernel_launch(void* const* d_in, const int* in_sizes, int n_in,
                              void* d_out, int out_size)
{
    (void)in_sizes; (void)n_in; (void)out_size;
    const float* x  = (const float*)d_in[0];
    const float* w1 = (const float*)d_in[1];
    const float* b1 = (const float*)d_in[2];
    const float* w2 = (const float*)d_in[3];
    const float* b2 = (const float*)d_in[4];
    const float* wr = (const float*)d_in[5];
    float* out = (float*)d_out;

    cudaFuncSetAttribute(k_fft_fwd, cudaFuncAttributeMaxDynamicSharedMemorySize, FFT_SMEM);
    cudaFuncSetAttribute(k_ifft,    cudaFuncAttributeMaxDynamicSharedMemorySize, FFT_SMEM);
    cudaFuncSetAttribute(k_conv,    cudaFuncAttributeMaxDynamicSharedMemorySize, CONV_SMEM);

    k_prep<<<NC*NC/256, 256>>>(wr);
    k_fft_fwd<<<NIMG, 1024, FFT_SMEM>>>(x);
    k_head<<<NB, 256>>>(w1, b1, w2, b2);
    k_conv<<<NIMG, 1024, CONV_SMEM>>>();
    k_gemm_tc<<<dim3(32768/128, NC/128, NB), 256>>>();
    k_ifft<<<NIMG, 1024, FFT_SMEM>>>(x, out);
}

// round 6
// speedup vs baseline: 2.8521x; 1.5427x over previous
#include <cuda_runtime.h>
#include <cuda_bf16.h>
#include <math.h>

// ---------------------------------------------------------------------------
// AFEModule: fft2(ortho) -> fftshift -> center-mag MLP -> aniso 7x7 kernel ->
// zero-pad conv of shifted spectrum -> 256x256 channel mix -> ifftshift ->
// ifft2(ortho).real + x
// ---------------------------------------------------------------------------

#define NB    8
#define NC    256
#define NIMG  2048
#define HW    128
#define NPIX  16384
#define LDS_  129
#define PLANE 16512

#define FFT_SMEM ((2*PLANE + 128) * 4)

#define CP    134
#define CPS   136
#define CONV_SMEM (2*CP*CPS*4)

// Scratch (device globals; allocation-free contract).
__device__ __align__(256) float2 g_xf[NIMG * (size_t)NPIX];             // spectra (shifted); reused as GEMM out
__device__ __align__(256) __nv_bfloat16 g_fhi[NIMG * (size_t)NPIX * 2]; // conv out hi (re,im interleaved)
__device__ __align__(256) __nv_bfloat16 g_flo[NIMG * (size_t)NPIX * 2]; // conv out lo
__device__ __align__(16)  __nv_bfloat16 g_wrhi[NC * NC];
__device__ __align__(16)  __nv_bfloat16 g_wrlo[NC * NC];
__device__ float g_kern[NB * 49];

__device__ __forceinline__ int brev7(int v) { return (int)(__brev((unsigned)v) >> 25); }

// ---------------------------------------------------------------------------
// 1-D DIF FFT over 128 lines: fused-pair rounds (6,5),(4,3), then radix-8
// round covering stages (2,1,0). Line-fast thread map: conflict-free in both
// row pass (lineStride=LDS_, elemStride=1) and col pass (1, LDS_).
// Natural-order in, bit-reversed out.
// ---------------------------------------------------------------------------
__device__ void fft_pass(float* sre, float* sim,
                         const float* twr, const float* twi,
                         int lineStride, int elemStride)
{
    #pragma unroll 1
    for (int s = 6; s >= 4; s -= 2) {
        const int q = 1 << (s - 1);
        for (int u = threadIdx.x; u < 4096; u += blockDim.x) {
            const int line = u & 127;
            const int t    = u >> 7;
            const int j    = t & (q - 1);
            const int base = ((t >> (s - 1)) << (s + 1)) | j;
            const int o0   = line * lineStride + base * elemStride;
            const int oq   = q * elemStride;

            float Ar = sre[o0],        Ai = sim[o0];
            float Br = sre[o0 + oq],   Bi = sim[o0 + oq];
            float Cr = sre[o0 + 2*oq], Ci = sim[o0 + 2*oq];
            float Dr = sre[o0 + 3*oq], Di = sim[o0 + 3*oq];

            const float w1r = twr[j << (6 - s)],       w1i = twi[j << (6 - s)];
            const float w2r = twr[(j + q) << (6 - s)], w2i = twi[(j + q) << (6 - s)];
            const float w3r = twr[j << (7 - s)],       w3i = twi[j << (7 - s)];

            float t0r = Ar + Cr, t0i = Ai + Ci;
            float d0r = Ar - Cr, d0i = Ai - Ci;
            float Cpr = d0r*w1r - d0i*w1i, Cpi = d0r*w1i + d0i*w1r;
            float t1r = Br + Dr, t1i = Bi + Di;
            float d1r = Br - Dr, d1i = Bi - Di;
            float Dpr = d1r*w2r - d1i*w2i, Dpi = d1r*w2i + d1i*w2r;

            sre[o0]        = t0r + t1r;  sim[o0]        = t0i + t1i;
            float e1r = t0r - t1r, e1i = t0i - t1i;
            sre[o0 + oq]   = e1r*w3r - e1i*w3i;
            sim[o0 + oq]   = e1r*w3i + e1i*w3r;
            sre[o0 + 2*oq] = Cpr + Dpr;  sim[o0 + 2*oq] = Cpi + Dpi;
            float e3r = Cpr - Dpr, e3i = Cpi - Dpi;
            sre[o0 + 3*oq] = e3r*w3r - e3i*w3i;
            sim[o0 + 3*oq] = e3r*w3i + e3i*w3r;
        }
        __syncthreads();
    }
    // radix-8 round: stages 2,1,0 within groups of 8 consecutive elements
    for (int u = threadIdx.x; u < 2048; u += blockDim.x) {
        const int line = u & 127;
        const int g    = u >> 7;                  // 0..15
        const int o0   = line * lineStride + (g << 3) * elemStride;
        float r[8], m[8];
        #pragma unroll
        for (int i = 0; i < 8; ++i) { r[i] = sre[o0 + i*elemStride]; m[i] = sim[o0 + i*elemStride]; }
        // stage 2 (dist 4), twiddle w^(i*16)
        #pragma unroll
        for (int i = 0; i < 4; ++i) {
            float tr = r[i] + r[i+4], tm = m[i] + m[i+4];
            float dr = r[i] - r[i+4], dm = m[i] - m[i+4];
            float wr_ = twr[i*16], wi_ = twi[i*16];
            r[i] = tr; m[i] = tm;
            r[i+4] = dr*wr_ - dm*wi_; m[i+4] = dr*wi_ + dm*wr_;
        }
        // stage 1 (dist 2), twiddle w^(i*32)
        #pragma unroll
        for (int g2 = 0; g2 < 8; g2 += 4) {
            #pragma unroll
            for (int i = 0; i < 2; ++i) {
                int a = g2 + i, bnd = a + 2;
                float tr = r[a] + r[bnd], tm = m[a] + m[bnd];
                float dr = r[a] - r[bnd], dm = m[a] - m[bnd];
                float wr_ = twr[i*32], wi_ = twi[i*32];
                r[a] = tr; m[a] = tm;
                r[bnd] = dr*wr_ - dm*wi_; m[bnd] = dr*wi_ + dm*wr_;
            }
        }
        // stage 0 (dist 1)
        #pragma unroll
        for (int a = 0; a < 8; a += 2) {
            float tr = r[a] + r[a+1], tm = m[a] + m[a+1];
            float dr = r[a] - r[a+1], dm = m[a] - m[a+1];
            r[a] = tr; m[a] = tm; r[a+1] = dr; m[a+1] = dm;
        }
        #pragma unroll
        for (int i = 0; i < 8; ++i) { sre[o0 + i*elemStride] = r[i]; sim[o0 + i*elemStride] = m[i]; }
    }
    __syncthreads();
}

// ---------------------------------------------------------------------------
// Forward FFT2 (ortho) of TWO real images packed as x1 + i*x2; separation +
// fftshift at store. Grid: NIMG/2 blocks.
// ---------------------------------------------------------------------------
__global__ void k_fft_fwd(const float* __restrict__ x)
{
    extern __shared__ float sm[];
    float* sre = sm;
    float* sim = sm + PLANE;
    float* twr = sm + 2*PLANE;
    float* twi = twr + 64;

    const int ia = 2*blockIdx.x;
    const float* x1 = x + (size_t)ia * NPIX;
    const float* x2 = x1 + NPIX;

    for (int t = threadIdx.x; t < 64; t += blockDim.x) {
        float sv, cv;
        sincosf(-6.283185307179586f * (float)t / 128.0f, &sv, &cv);
        twr[t] = cv; twi[t] = sv;
    }
    for (int i = threadIdx.x; i < NPIX; i += blockDim.x) {
        int y = i >> 7, xx = i & 127;
        sre[y*LDS_ + xx] = x1[i];
        sim[y*LDS_ + xx] = x2[i];
    }
    __syncthreads();

    fft_pass(sre, sim, twr, twi, LDS_, 1);   // rows
    fft_pass(sre, sim, twr, twi, 1, LDS_);   // cols

    float2* d1 = g_xf + (size_t)ia * NPIX;
    float2* d2 = d1 + NPIX;
    const float sc = 1.0f / 128.0f;
    for (int i = threadIdx.x; i < NPIX; i += blockDim.x) {
        const int u = i >> 7, v = i & 127;
        const int un = (128 - u) & 127, vn = (128 - v) & 127;
        const int j = un*128 + vn;
        if (i > j) continue;
        float Wr = sre[brev7(u)*LDS_ + brev7(v)],  Wi = sim[brev7(u)*LDS_ + brev7(v)];
        float Nr = sre[brev7(un)*LDS_ + brev7(vn)], Ni = sim[brev7(un)*LDS_ + brev7(vn)];
        float x1r = 0.5f*(Wr + Nr), x1i = 0.5f*(Wi - Ni);
        float dr  = 0.5f*(Wr - Nr), di  = 0.5f*(Wi + Ni);
        float x2r = di, x2i = -dr;
        const int si = ((u+64)&127)*128 + ((v+64)&127);
        const int sj = ((un+64)&127)*128 + ((vn+64)&127);
        d1[si] = make_float2(x1r*sc,  x1i*sc);
        d2[si] = make_float2(x2r*sc,  x2i*sc);
        d1[sj] = make_float2(x1r*sc, -x1i*sc);
        d2[sj] = make_float2(x2r*sc, -x2i*sc);
    }
}

// ---------------------------------------------------------------------------
// Head: warp-parallel channel reductions; MLP + aniso kernel.
// ---------------------------------------------------------------------------
__global__ void k_head(const float* __restrict__ w1, const float* __restrict__ b1,
                       const float* __restrict__ w2, const float* __restrict__ b2)
{
    __shared__ float center[49];
    __shared__ float hid[32];
    __shared__ float par[3];
    __shared__ float kk[50];

    const int b = blockIdx.x;
    const int tid  = threadIdx.x;
    const int lane = tid & 31;
    const int warp = tid >> 5;

    for (int p = warp; p < 49; p += 8) {
        const int h = 61 + p / 7, w = 61 + p % 7;
        float s = 0.0f;
        for (int c = lane; c < NC; c += 32) {
            float2 v = g_xf[((size_t)b * NC + c) * NPIX + h*128 + w];
            s += sqrtf(v.x*v.x + v.y*v.y);
        }
        #pragma unroll
        for (int o = 16; o; o >>= 1) s += __shfl_down_sync(0xFFFFFFFFu, s, o);
        if (lane == 0) center[p] = s * (1.0f / 256.0f);
    }
    __syncthreads();

    if (tid < 32) {
        float acc = b1[tid];
        for (int p = 0; p < 49; ++p) acc += center[p] * w1[p*32 + tid];
        hid[tid] = fmaxf(acc, 0.0f);
    }
    __syncthreads();
    if (tid < 3) {
        float acc = b2[tid];
        for (int j = 0; j < 32; ++j) acc += hid[j] * w2[j*3 + tid];
        par[tid] = acc;
    }
    __syncthreads();
    if (tid < 49) {
        float theta = atan2f(par[0], par[1]) * 0.5f + 1.5707963267948966f;
        float lam1  = expf(par[2]);
        float lam2  = 1.0f / (lam1 + 1e-8f);
        float ct, st;
        sincosf(theta, &st, &ct);
        float yy = (float)(tid / 7) - 3.0f;
        float xx = (float)(tid % 7) - 3.0f;
        float xr =  xx*ct + yy*st;
        float yr = -xx*st + yy*ct;
        kk[tid] = expf(-(xr*xr / (2.0f*lam1*lam1) + yr*yr / (2.0f*lam2*lam2)));
    }
    __syncthreads();
    if (tid == 0) {
        float s = 0.0f;
        for (int i = 0; i < 49; ++i) s += kk[i];
        kk[49] = s + 1e-8f;
    }
    __syncthreads();
    if (tid < 49) g_kern[b*49 + tid] = kk[tid] / kk[49];
}

// ---------------------------------------------------------------------------
__global__ void k_prep(const float* __restrict__ wr)
{
    int i = blockIdx.x * 256 + threadIdx.x;
    float v = wr[i];
    __nv_bfloat16 h = __float2bfloat16(v);
    g_wrhi[i] = h;
    g_wrlo[i] = __float2bfloat16(v - __bfloat162float(h));
}

// ---------------------------------------------------------------------------
// 7x7 zero-pad conv; 8x4 register tiles (sliding 10-row window); bf16 hi/lo out.
// ---------------------------------------------------------------------------
__global__ void __launch_bounds__(512) k_conv()
{
    extern __shared__ float sm[];
    float* sre = sm;
    float* sim = sm + CP*CPS;
    __shared__ float kk[49];

    const int img = blockIdx.x;
    const int b   = img >> 8;
    const int tid = threadIdx.x;

    if (tid < 49) kk[tid] = g_kern[b*49 + tid];
    for (int i = tid; i < 2*CP*CPS; i += 512) sm[i] = 0.0f;
    __syncthreads();

    const float2* src = g_xf + (size_t)img * NPIX;
    for (int i = tid; i < NPIX; i += 512) {
        int y = i >> 7, x = i & 127;
        float2 v = src[i];
        sre[(y+3)*CPS + (x+3)] = v.x;
        sim[(y+3)*CPS + (x+3)] = v.y;
    }
    __syncthreads();

    const int y0 = (tid >> 4) << 2;   // 0..124
    const int x0 = (tid & 15) << 3;   // 0..120

    float ar[4][8], ai[4][8];
    #pragma unroll
    for (int r = 0; r < 4; ++r)
        #pragma unroll
        for (int p = 0; p < 8; ++p) { ar[r][p] = 0.0f; ai[r][p] = 0.0f; }

    #pragma unroll
    for (int ri = 0; ri < 10; ++ri) {
        const float* pr = &sre[(y0 + ri)*CPS + x0];
        const float* pi = &sim[(y0 + ri)*CPS + x0];
        float re[16], im[16];
        *(float4*)&re[0]  = *(const float4*)&pr[0];
        *(float4*)&re[4]  = *(const float4*)&pr[4];
        *(float4*)&re[8]  = *(const float4*)&pr[8];
        *(float4*)&re[12] = *(const float4*)&pr[12];
        *(float4*)&im[0]  = *(const float4*)&pi[0];
        *(float4*)&im[4]  = *(const float4*)&pi[4];
        *(float4*)&im[8]  = *(const float4*)&pi[8];
        *(float4*)&im[12] = *(const float4*)&pi[12];
        #pragma unroll
        for (int r = 0; r < 4; ++r) {
            const int dy = ri - r;
            if (dy < 0 || dy > 6) continue;
            #pragma unroll
            for (int dx = 0; dx < 7; ++dx) {
                float w = kk[dy*7 + dx];
                #pragma unroll
                for (int p = 0; p < 8; ++p) {
                    ar[r][p] = fmaf(w, re[dx+p], ar[r][p]);
                    ai[r][p] = fmaf(w, im[dx+p], ai[r][p]);
                }
            }
        }
    }

    __nv_bfloat162* dh = (__nv_bfloat162*)(g_fhi + (size_t)img * NPIX * 2);
    __nv_bfloat162* dl = (__nv_bfloat162*)(g_flo + (size_t)img * NPIX * 2);
    #pragma unroll
    for (int r = 0; r < 4; ++r) {
        const int o = (y0 + r)*128 + x0;
        #pragma unroll
        for (int p = 0; p < 8; ++p) {
            __nv_bfloat16 hr = __float2bfloat16(ar[r][p]);
            __nv_bfloat16 hi = __float2bfloat16(ai[r][p]);
            dh[o + p] = __nv_bfloat162(hr, hi);
            __nv_bfloat16 lr = __float2bfloat16(ar[r][p] - __bfloat162float(hr));
            __nv_bfloat16 li = __float2bfloat16(ai[r][p] - __bfloat162float(hi));
            dl[o + p] = __nv_bfloat162(lr, li);
        }
    }
}

// ---------------------------------------------------------------------------
// Tensor-core channel-mix GEMM (bf16x3): C = Ah*Bh + Ah*Bl + Al*Bh.
// ---------------------------------------------------------------------------
#define SWS 40
#define SFS 136

__device__ __forceinline__ void ldsm_x4(unsigned& r0, unsigned& r1, unsigned& r2, unsigned& r3,
                                        unsigned addr)
{
    asm volatile("ldmatrix.sync.aligned.m8n8.x4.shared.b16 {%0,%1,%2,%3}, [%4];"
                 : "=r"(r0), "=r"(r1), "=r"(r2), "=r"(r3) : "r"(addr));
}
__device__ __forceinline__ void ldsm_x4_t(unsigned& r0, unsigned& r1, unsigned& r2, unsigned& r3,
                                          unsigned addr)
{
    asm volatile("ldmatrix.sync.aligned.m8n8.x4.trans.shared.b16 {%0,%1,%2,%3}, [%4];"
                 : "=r"(r0), "=r"(r1), "=r"(r2), "=r"(r3) : "r"(addr));
}
__device__ __forceinline__ void mma16816(float* c, const unsigned* a, const unsigned* b)
{
    asm volatile("mma.sync.aligned.m16n8k16.row.col.f32.bf16.bf16.f32 "
                 "{%0,%1,%2,%3}, {%4,%5,%6,%7}, {%8,%9}, {%0,%1,%2,%3};"
                 : "+f"(c[0]), "+f"(c[1]), "+f"(c[2]), "+f"(c[3])
                 : "r"(a[0]), "r"(a[1]), "r"(a[2]), "r"(a[3]), "r"(b[0]), "r"(b[1]));
}

__global__ void __launch_bounds__(256) k_gemm_tc()
{
    __shared__ __nv_bfloat16 sWh[128*SWS], sWl[128*SWS];
    __shared__ __nv_bfloat16 sFh[32*SFS],  sFl[32*SFS];

    const int b     = blockIdx.z;
    const int oBase = blockIdx.y * 128;
    const int pBase = blockIdx.x * 128;
    const int tid   = threadIdx.x;
    const int lane  = tid & 31;
    const int warp  = tid >> 5;
    const int wo    = warp >> 1;
    const int wp    = warp & 1;

    const __nv_bfloat16* Fh = g_fhi + (size_t)b * NC * 32768;
    const __nv_bfloat16* Fl = g_flo + (size_t)b * NC * 32768;

    const unsigned swh = (unsigned)__cvta_generic_to_shared(sWh);
    const unsigned swl = (unsigned)__cvta_generic_to_shared(sWl);
    const unsigned sfh = (unsigned)__cvta_generic_to_shared(sFh);
    const unsigned sfl = (unsigned)__cvta_generic_to_shared(sFl);

    float acc[2][8][4];
    #pragma unroll
    for (int m = 0; m < 2; ++m)
        #pragma unroll
        for (int n = 0; n < 8; ++n)
            #pragma unroll
            for (int q = 0; q < 4; ++q) acc[m][n][q] = 0.0f;

    const int aRow  = lane & 15;
    const int aKof  = (lane >> 4) << 3;
    const int bKrow = lane & 15;
    const int bPof  = (lane >> 4) << 3;

    for (int k0 = 0; k0 < NC; k0 += 32) {
        #pragma unroll
        for (int t = 0; t < 2; ++t) {
            int id = tid + t*256;
            int o  = id >> 2, kc = (id & 3) << 3;
            *(uint4*)&sWh[o*SWS + kc] = *(const uint4*)&g_wrhi[(oBase + o)*NC + k0 + kc];
            *(uint4*)&sWl[o*SWS + kc] = *(const uint4*)&g_wrlo[(oBase + o)*NC + k0 + kc];
        }
        #pragma unroll
        for (int t = 0; t < 2; ++t) {
            int id = tid + t*256;
            int k  = id >> 4, pc = (id & 15) << 3;
            *(uint4*)&sFh[k*SFS + pc] = *(const uint4*)&Fh[(size_t)(k0 + k)*32768 + pBase + pc];
            *(uint4*)&sFl[k*SFS + pc] = *(const uint4*)&Fl[(size_t)(k0 + k)*32768 + pBase + pc];
        }
        __syncthreads();

        #pragma unroll
        for (int kk = 0; kk < 32; kk += 16) {
            unsigned ah[2][4], al[2][4];
            #pragma unroll
            for (int mt = 0; mt < 2; ++mt) {
                unsigned off = ((wo*32 + mt*16 + aRow)*SWS + kk + aKof) * 2;
                ldsm_x4(ah[mt][0], ah[mt][1], ah[mt][2], ah[mt][3], swh + off);
                ldsm_x4(al[mt][0], al[mt][1], al[mt][2], al[mt][3], swl + off);
            }
            unsigned bh[8][2], bl[8][2];
            #pragma unroll
            for (int ng = 0; ng < 4; ++ng) {
                unsigned off = ((kk + bKrow)*SFS + wp*64 + ng*16 + bPof) * 2;
                ldsm_x4_t(bh[2*ng][0], bh[2*ng][1], bh[2*ng+1][0], bh[2*ng+1][1], sfh + off);
                ldsm_x4_t(bl[2*ng][0], bl[2*ng][1], bl[2*ng+1][0], bl[2*ng+1][1], sfl + off);
            }
            #pragma unroll
            for (int mt = 0; mt < 2; ++mt)
                #pragma unroll
                for (int nt = 0; nt < 8; ++nt) {
                    mma16816(acc[mt][nt], ah[mt], bh[nt]);
                    mma16816(acc[mt][nt], ah[mt], bl[nt]);
                    mma16816(acc[mt][nt], al[mt], bh[nt]);
                }
        }
        __syncthreads();
    }

    float* O = (float*)(g_xf + (size_t)b * NC * NPIX);
    const int cRow = lane >> 2;
    const int cCol = (lane & 3) << 1;
    #pragma unroll
    for (int mt = 0; mt < 2; ++mt) {
        #pragma unroll
        for (int nt = 0; nt < 8; ++nt) {
            size_t o0 = (size_t)(oBase + wo*32 + mt*16 + cRow);
            size_t p  = (size_t)(pBase + wp*64 + nt*8 + cCol);
            *(float2*)&O[o0*32768 + p]     = make_float2(acc[mt][nt][0], acc[mt][nt][1]);
            *(float2*)&O[(o0+8)*32768 + p] = make_float2(acc[mt][nt][2], acc[mt][nt][3]);
        }
    }
}

// ---------------------------------------------------------------------------
// Inverse FFT2 (ortho) of TWO channels: Hermitian-project each spectrum
// (exactly Re(IFFT)), pack Zh1 + i*Zh2, one complex IFFT; Re/Im planes are the
// two outputs. ifftshift folded into the load. Fused ".real + x".
// ---------------------------------------------------------------------------
__global__ void k_ifft(const float* __restrict__ x, float* __restrict__ out)
{
    extern __shared__ float sm[];
    float* sre = sm;
    float* sim = sm + PLANE;
    float* twr = sm + 2*PLANE;
    float* twi = twr + 64;

    const int ia = 2*blockIdx.x;
    const float2* s1 = g_xf + (size_t)ia * NPIX;
    const float2* s2 = s1 + NPIX;

    for (int t = threadIdx.x; t < 64; t += blockDim.x) {
        float sv, cv;
        sincosf(6.283185307179586f * (float)t / 128.0f, &sv, &cv);
        twr[t] = cv; twi[t] = sv;
    }
    for (int i = threadIdx.x; i < NPIX; i += blockDim.x) {
        const int u = i >> 7, v = i & 127;
        const int un = (128 - u) & 127, vn = (128 - v) & 127;
        const int j = un*128 + vn;
        if (i > j) continue;
        const int si = ((u+64)&127)*128 + ((v+64)&127);
        const int sj = ((un+64)&127)*128 + ((vn+64)&127);
        float2 A1 = s1[si], B1 = s1[sj];
        float2 A2 = s2[si], B2 = s2[sj];
        float r1 = 0.5f*(A1.x + B1.x), m1 = 0.5f*(A1.y - B1.y);
        float r2 = 0.5f*(A2.x + B2.x), m2 = 0.5f*(A2.y - B2.y);
        sre[u*LDS_ + v]   = r1 - m2;  sim[u*LDS_ + v]   = m1 + r2;
        sre[un*LDS_ + vn] = r1 + m2;  sim[un*LDS_ + vn] = r2 - m1;
    }
    __syncthreads();

    fft_pass(sre, sim, twr, twi, LDS_, 1);
    fft_pass(sre, sim, twr, twi, 1, LDS_);

    const float* x1 = x + (size_t)ia * NPIX;
    const float* x2 = x1 + NPIX;
    float* d1 = out + (size_t)ia * NPIX;
    float* d2 = d1 + NPIX;
    const float sc = 1.0f / 128.0f;
    for (int i = threadIdx.x; i < NPIX; i += blockDim.x) {
        int u = i >> 7, v = i & 127;
        int o = brev7(u)*LDS_ + brev7(v);
        d1[i] = sre[o] * sc + x1[i];
        d2[i] = sim[o] * sc + x2[i];
    }
}

// ---------------------------------------------------------------------------
extern "C" void kernel_launch(void* const* d_in, const int* in_sizes, int n_in,
                              void* d_out, int out_size)
{
    (void)in_sizes; (void)n_in; (void)out_size;
    const float* x  = (const float*)d_in[0];
    const float* w1 = (const float*)d_in[1];
    const float* b1 = (const float*)d_in[2];
    const float* w2 = (const float*)d_in[3];
    const float* b2 = (const float*)d_in[4];
    const float* wr = (const float*)d_in[5];
    float* out = (float*)d_out;

    cudaFuncSetAttribute(k_fft_fwd, cudaFuncAttributeMaxDynamicSharedMemorySize, FFT_SMEM);
    cudaFuncSetAttribute(k_ifft,    cudaFuncAttributeMaxDynamicSharedMemorySize, FFT_SMEM);
    cudaFuncSetAttribute(k_conv,    cudaFuncAttributeMaxDynamicSharedMemorySize, CONV_SMEM);

    k_prep<<<NC*NC/256, 256>>>(wr);
    k_fft_fwd<<<NIMG/2, 1024, FFT_SMEM>>>(x);
    k_head<<<NB, 256>>>(w1, b1, w2, b2);
    k_conv<<<NIMG, 512, CONV_SMEM>>>();
    k_gemm_tc<<<dim3(32768/128, NC/128, NB), 256>>>();
    k_ifft<<<NIMG/2, 1024, FFT_SMEM>>>(x, out);
}